// round 9
// baseline (speedup 1.0000x reference)
#include <cuda_runtime.h>
#include <cuda_fp16.h>
#include <math_constants.h>
#include <cstdint>

// ---------------------------------------------------------------------------
// RPE_Attention: x[64,197,768] -> qkv -> per-head attention (+rel pos bias) ->
// proj.
// GEMMs: fp16 mma.sync 3-term Markidis split; NEW geometry: 256x128 block,
//        8 warps (4x2), warp tile 64x64, BK=16 -> 2x HMMA per LDS byte
//        (smem-BW bound -> mma-bound).
// Attention: tensorized mma.sync (R8, proven).
// ---------------------------------------------------------------------------

#define BATCH 64
#define NQ    197
#define CDIM  768
#define NH    12
#define HD    64
#define NP    196
#define MTOT  (BATCH * NQ)          // 12608

// fp32 scratch
__device__ float g_qkv[(size_t)MTOT * 3 * CDIM];
__device__ float g_attn[(size_t)MTOT * CDIM];

// pre-split fp16 planes for GEMMs
__device__ __half2 g_xhi[(size_t)MTOT * CDIM / 2];
__device__ __half2 g_xlo[(size_t)MTOT * CDIM / 2];
__device__ __half2 g_whi[(size_t)3 * CDIM * CDIM / 2];
__device__ __half2 g_wlo[(size_t)3 * CDIM * CDIM / 2];
__device__ __half2 g_phi[(size_t)CDIM * CDIM / 2];
__device__ __half2 g_plo[(size_t)CDIM * CDIM / 2];
__device__ __half2 g_ahi[(size_t)MTOT * CDIM / 2];
__device__ __half2 g_alo[(size_t)MTOT * CDIM / 2];

// ===========================================================================
// common helpers
// ===========================================================================
__device__ __forceinline__ unsigned smem_u32(const void* p) {
    return (unsigned)__cvta_generic_to_shared(p);
}
__device__ __forceinline__ void cp_async16(unsigned dst, const void* src, bool pred) {
    int sz = pred ? 16 : 0;
    asm volatile("cp.async.cg.shared.global [%0], [%1], 16, %2;\n"
                 :: "r"(dst), "l"(src), "r"(sz));
}
__device__ __forceinline__ void cp_commit() { asm volatile("cp.async.commit_group;\n"); }
__device__ __forceinline__ void cp_wait0()  { asm volatile("cp.async.wait_group 0;\n"); }

__device__ __forceinline__ void ldsm_x4(uint32_t* r, unsigned a) {
    asm volatile("ldmatrix.sync.aligned.m8n8.x4.shared.b16 {%0,%1,%2,%3}, [%4];"
                 : "=r"(r[0]), "=r"(r[1]), "=r"(r[2]), "=r"(r[3]) : "r"(a));
}
__device__ __forceinline__ void ldsm_x2(uint32_t& r0, uint32_t& r1, unsigned a) {
    asm volatile("ldmatrix.sync.aligned.m8n8.x2.shared.b16 {%0,%1}, [%2];"
                 : "=r"(r0), "=r"(r1) : "r"(a));
}
__device__ __forceinline__ void mma_f16(float* d, const uint32_t* a, const uint32_t* b) {
    asm volatile(
        "mma.sync.aligned.m16n8k16.row.col.f32.f16.f16.f32 "
        "{%0,%1,%2,%3}, {%4,%5,%6,%7}, {%8,%9}, {%0,%1,%2,%3};"
        : "+f"(d[0]), "+f"(d[1]), "+f"(d[2]), "+f"(d[3])
        : "r"(a[0]), "r"(a[1]), "r"(a[2]), "r"(a[3]), "r"(b[0]), "r"(b[1]));
}

// ===========================================================================
// split: fp32 -> (hi, lo) fp16 planes.
// ===========================================================================
__global__ void split_h(const float4* __restrict__ src, __half2* __restrict__ hi,
                        __half2* __restrict__ lo, int n4)
{
    int i = blockIdx.x * blockDim.x + threadIdx.x;
    if (i >= n4) return;
    float4 v = src[i];
    __half2 h0 = __floats2half2_rn(v.x, v.y);
    __half2 h1 = __floats2half2_rn(v.z, v.w);
    float2 f0 = __half22float2(h0);
    float2 f1 = __half22float2(h1);
    __half2 l0 = __floats2half2_rn(v.x - f0.x, v.y - f0.y);
    __half2 l1 = __floats2half2_rn(v.z - f1.x, v.w - f1.y);
    hi[2 * i]     = h0;
    hi[2 * i + 1] = h1;
    lo[2 * i]     = l0;
    lo[2 * i + 1] = l1;
}

// ===========================================================================
// fp16-split GEMM (NT), v2: BM=256, BN=128, BK=16, 256 thr = 8 warps (4x2),
// warp tile 64x64.  Row stride 24 halfs (48B, conflict-free for ldmatrix).
// SMEM per buffer: [Ahi 256x24][Alo 256x24][Bhi 128x24][Blo 128x24]
// ===========================================================================
#define S24   24
#define ASZ   (256 * S24)              // 6144 halfs
#define BSZ   (128 * S24)              // 3072 halfs
#define BUFH2 (2 * ASZ + 2 * BSZ)      // 18432 halfs
#define G2SMEM (2 * BUFH2 * 2)         // 73728 bytes

__global__ __launch_bounds__(256, 1) void gemm_f16s2(
    const __half* __restrict__ Ahi, const __half* __restrict__ Alo,
    const __half* __restrict__ Bhi, const __half* __restrict__ Blo,
    const float* __restrict__ bias, float* __restrict__ C,
    int M, int N, int K)
{
    extern __shared__ __half smg[];

    const int tid  = threadIdx.x;
    const int lane = tid & 31;
    const int wid  = tid >> 5;
    const int wm   = wid & 3;          // 0..3  (64-row band of 256)
    const int wn   = wid >> 2;         // 0..1  (64-col band of 128)
    const int bm   = blockIdx.y * 256;
    const int bn   = blockIdx.x * 128;
    const unsigned sbase = smem_u32(smg);
    const unsigned BUFB = BUFH2 * 2;   // bytes per buffer

    // loader precompute ----------------------------------------------------
    // A: 512 segs of 16B per plane: seg = tid + 256*q; row = seg>>1; hh = seg&1
    // B: 256 segs: seg = tid; row = seg>>1; hh = seg&1
    const int ar0 = (tid + 0)   >> 1, ah0 = (tid & 1);
    const int ar1 = (tid + 256) >> 1, ah1 = (tid & 1);    // seg&1 same parity
    const int br  = tid >> 1,        bh = (tid & 1);
    const bool aok0 = (bm + ar0) < M;
    const bool aok1 = (bm + ar1) < M;
    const __half* gA0h = Ahi + (size_t)(aok0 ? bm + ar0 : 0) * K + ah0 * 8;
    const __half* gA0l = Alo + (size_t)(aok0 ? bm + ar0 : 0) * K + ah0 * 8;
    const __half* gA1h = Ahi + (size_t)(aok1 ? bm + ar1 : 0) * K + ah1 * 8;
    const __half* gA1l = Alo + (size_t)(aok1 ? bm + ar1 : 0) * K + ah1 * 8;
    const __half* gBh  = Bhi + (size_t)(bn + br) * K + bh * 8;
    const __half* gBl  = Blo + (size_t)(bn + br) * K + bh * 8;
    const unsigned sA0 = sbase + (unsigned)(ar0 * S24 + ah0 * 8) * 2u;
    const unsigned sA1 = sbase + (unsigned)(ar1 * S24 + ah1 * 8) * 2u;
    const unsigned sB  = sbase + (unsigned)(2 * ASZ + br * S24 + bh * 8) * 2u;

    auto load_chunk = [&](int k0, int buf) {
        const unsigned off = (unsigned)buf * BUFB;
        cp_async16(sA0 + off,           gA0h + k0, aok0);
        cp_async16(sA0 + off + ASZ * 2, gA0l + k0, aok0);
        cp_async16(sA1 + off,           gA1h + k0, aok1);
        cp_async16(sA1 + off + ASZ * 2, gA1l + k0, aok1);
        cp_async16(sB  + off,           gBh  + k0, true);
        cp_async16(sB  + off + BSZ * 2, gBl  + k0, true);
        cp_commit();
    };

    const int nIter = K / 16;          // 48

    float acc[4][8][4];
#pragma unroll
    for (int i = 0; i < 4; i++)
#pragma unroll
        for (int j = 0; j < 8; j++)
#pragma unroll
            for (int r = 0; r < 4; r++) acc[i][j][r] = 0.f;

    load_chunk(0, 0);

    // fragment address bases
    const int arow = wm * 64 + (lane & 15);
    const int acol = (lane >> 4) * 8;
    const int brow = wn * 64 + (lane & 7);
    const int bcol = ((lane >> 3) & 1) * 8;

    for (int it = 0; it < nIter; it++) {
        cp_wait0();
        __syncthreads();

        if (it + 1 < nIter) load_chunk((it + 1) * 16, (it + 1) & 1);

        const unsigned boff = (unsigned)(it & 1) * BUFB;
        const __half* sa0 = smg + (it & 1) * BUFH2;
        const __half* sa1 = sa0 + ASZ;
        const __half* sb0 = smg + (it & 1) * BUFH2 + 2 * ASZ;
        const __half* sb1 = sb0 + BSZ;
        (void)boff;

        // B fragments: 8 nt x 2 planes
        uint32_t bhf[8][2], blf[8][2];
#pragma unroll
        for (int nt = 0; nt < 8; nt++) {
            ldsm_x2(bhf[nt][0], bhf[nt][1], smem_u32(sb0 + (brow + nt * 8) * S24 + bcol));
            ldsm_x2(blf[nt][0], blf[nt][1], smem_u32(sb1 + (brow + nt * 8) * S24 + bcol));
        }
#pragma unroll
        for (int mt = 0; mt < 4; mt++) {
            uint32_t ah[4], al[4];
            ldsm_x4(ah, smem_u32(sa0 + (arow + mt * 16) * S24 + acol));
            ldsm_x4(al, smem_u32(sa1 + (arow + mt * 16) * S24 + acol));
#pragma unroll
            for (int nt = 0; nt < 8; nt++) mma_f16(acc[mt][nt], ah, bhf[nt]);
#pragma unroll
            for (int nt = 0; nt < 8; nt++) mma_f16(acc[mt][nt], al, bhf[nt]);
#pragma unroll
            for (int nt = 0; nt < 8; nt++) mma_f16(acc[mt][nt], ah, blf[nt]);
        }
        __syncthreads();
    }

    // epilogue
    const int g = lane >> 2;
    const int t = lane & 3;
#pragma unroll
    for (int mt = 0; mt < 4; mt++) {
        const int r0 = bm + wm * 64 + mt * 16 + g;
#pragma unroll
        for (int nt = 0; nt < 8; nt++) {
            const int col = bn + wn * 64 + nt * 8 + 2 * t;
            const float bv0 = bias ? bias[col]     : 0.f;
            const float bv1 = bias ? bias[col + 1] : 0.f;
            if (r0 < M) {
                float2 v = make_float2(acc[mt][nt][0] + bv0, acc[mt][nt][1] + bv1);
                *(float2*)&C[(size_t)r0 * N + col] = v;
            }
            if (r0 + 8 < M) {
                float2 v = make_float2(acc[mt][nt][2] + bv0, acc[mt][nt][3] + bv1);
                *(float2*)&C[(size_t)(r0 + 8) * N + col] = v;
            }
        }
    }
}

// ===========================================================================
// Tensorized attention (R8, unchanged): block per (b,h), 256 threads.
// ===========================================================================
#define NPAD   208
#define QKS    72
#define VTS    232
#define QH_OFF 0
#define QL_OFF (NPAD * QKS)
#define KH_OFF (2 * NPAD * QKS)
#define KL_OFF (3 * NPAD * QKS)
#define VTH_OFF (4 * NPAD * QKS)
#define VTL_OFF (VTH_OFF + HD * VTS)
#define ATM_HALFS (VTL_OFF + HD * VTS)
#define ATM_SMEM  (ATM_HALFS * 2 + 736 * 4)

__device__ __forceinline__ void pack2(float x, float y, uint32_t& hi, uint32_t& lo) {
    __half2 h = __floats2half2_rn(x, y);
    float2 f = __half22float2(h);
    __half2 l = __floats2half2_rn(x - f.x, y - f.y);
    hi = *reinterpret_cast<uint32_t*>(&h);
    lo = *reinterpret_cast<uint32_t*>(&l);
}

__global__ __launch_bounds__(256, 1) void attn_mma(
    const float* __restrict__ qkv, const float* __restrict__ rpb_table,
    const int* __restrict__ rel_idx, float* __restrict__ out)
{
    extern __shared__ __align__(16) __half sma[];
    __half* QH  = sma + QH_OFF;
    __half* QL  = sma + QL_OFF;
    __half* KH  = sma + KH_OFF;
    __half* KL  = sma + KL_OFF;
    __half* VTH = sma + VTH_OFF;
    __half* VTL = sma + VTL_OFF;
    float*  bias_s = (float*)(sma + ATM_HALFS);

    const int tid  = threadIdx.x;
    const int lane = tid & 31;
    const int wid  = tid >> 5;
    const int b = blockIdx.x / NH;
    const int h = blockIdx.x % NH;

    const float* base0 = qkv + (size_t)b * NQ * (3 * CDIM) + h * HD;
    for (int i = tid; i < NPAD * HD; i += 256) {
        const int n = i >> 6, d = i & 63;
        float qv = 0.f, kv = 0.f, vv = 0.f;
        if (n < NQ) {
            const float* p = base0 + (size_t)n * (3 * CDIM) + d;
            qv = p[0] * 0.125f;
            kv = p[CDIM];
            vv = p[2 * CDIM];
        }
        __half qh_ = __float2half_rn(qv);
        QH[n * QKS + d] = qh_;
        QL[n * QKS + d] = __float2half_rn(qv - __half2float(qh_));
        __half kh_ = __float2half_rn(kv);
        KH[n * QKS + d] = kh_;
        KL[n * QKS + d] = __float2half_rn(kv - __half2float(kh_));
        __half vh_ = __float2half_rn(vv);
        VTH[d * VTS + n] = vh_;
        VTL[d * VTS + n] = __float2half_rn(vv - __half2float(vh_));
    }
    for (int i = tid; i < 729; i += 256) bias_s[i] = rpb_table[i * NH + h];
    __syncthreads();

    const int g = lane >> 2;
    const int t = lane & 3;
    const int idx = lane >> 3;

    for (int mt = wid; mt < 13; mt += 8) {
        const int q0 = mt * 16;

        uint32_t qfh[4][4], qfl[4][4];
        {
            const int row = q0 + (lane & 15);
            const int col = (lane >> 4) * 8;
#pragma unroll
            for (int kt = 0; kt < 4; kt++) {
                ldsm_x4(qfh[kt], smem_u32(QH + row * QKS + kt * 16 + col));
                ldsm_x4(qfl[kt], smem_u32(QL + row * QKS + kt * 16 + col));
            }
        }

        float sc[26][4];
#pragma unroll
        for (int nt = 0; nt < 26; nt++)
#pragma unroll
            for (int e = 0; e < 4; e++) sc[nt][e] = 0.f;

#pragma unroll
        for (int ntp = 0; ntp < 13; ntp++) {
            const int row = ntp * 16 + (idx >> 1) * 8 + (lane & 7);
            const int col = (idx & 1) * 8;
            uint32_t kf[4][4], lf[4][4];
#pragma unroll
            for (int kt = 0; kt < 4; kt++) {
                ldsm_x4(kf[kt], smem_u32(KH + row * QKS + kt * 16 + col));
                ldsm_x4(lf[kt], smem_u32(KL + row * QKS + kt * 16 + col));
            }
#pragma unroll
            for (int kt = 0; kt < 4; kt++) {
                mma_f16(sc[2 * ntp],     qfh[kt], &kf[kt][0]);
                mma_f16(sc[2 * ntp + 1], qfh[kt], &kf[kt][2]);
                mma_f16(sc[2 * ntp],     qfl[kt], &kf[kt][0]);
                mma_f16(sc[2 * ntp + 1], qfl[kt], &kf[kt][2]);
                mma_f16(sc[2 * ntp],     qfh[kt], &lf[kt][0]);
                mma_f16(sc[2 * ntp + 1], qfh[kt], &lf[kt][2]);
            }
        }

        const int qa = q0 + g;
        const int qb = q0 + g + 8;
        const bool va = qa < NQ;
        const bool vb = qb < NQ;
#pragma unroll
        for (int nt = 0; nt < 26; nt++) {
            const int j0 = nt * 8 + 2 * t;
            const int j1 = j0 + 1;
            {
                float s = sc[nt][0];
                if (!va) s = 0.f;
                else if (j0 >= NQ) s = -CUDART_INF_F;
                else if (qa > 0 && j0 > 0)
                    s += bias_s[__ldg(rel_idx + (qa - 1) * NP + (j0 - 1))];
                sc[nt][0] = s;
            }
            {
                float s = sc[nt][1];
                if (!va) s = 0.f;
                else if (j1 >= NQ) s = -CUDART_INF_F;
                else if (qa > 0)
                    s += bias_s[__ldg(rel_idx + (qa - 1) * NP + (j1 - 1))];
                sc[nt][1] = s;
            }
            {
                float s = sc[nt][2];
                if (!vb) s = 0.f;
                else if (j0 >= NQ) s = -CUDART_INF_F;
                else if (qb > 0 && j0 > 0)
                    s += bias_s[__ldg(rel_idx + (qb - 1) * NP + (j0 - 1))];
                sc[nt][2] = s;
            }
            {
                float s = sc[nt][3];
                if (!vb) s = 0.f;
                else if (j1 >= NQ) s = -CUDART_INF_F;
                else if (qb > 0)
                    s += bias_s[__ldg(rel_idx + (qb - 1) * NP + (j1 - 1))];
                sc[nt][3] = s;
            }
        }

        float mA = -CUDART_INF_F, mB = -CUDART_INF_F;
#pragma unroll
        for (int nt = 0; nt < 26; nt++) {
            mA = fmaxf(mA, fmaxf(sc[nt][0], sc[nt][1]));
            mB = fmaxf(mB, fmaxf(sc[nt][2], sc[nt][3]));
        }
        mA = fmaxf(mA, __shfl_xor_sync(0xffffffffu, mA, 1));
        mA = fmaxf(mA, __shfl_xor_sync(0xffffffffu, mA, 2));
        mB = fmaxf(mB, __shfl_xor_sync(0xffffffffu, mB, 1));
        mB = fmaxf(mB, __shfl_xor_sync(0xffffffffu, mB, 2));

        float eA = 0.f, eB = 0.f;
#pragma unroll
        for (int nt = 0; nt < 26; nt++) {
            sc[nt][0] = __expf(sc[nt][0] - mA);
            sc[nt][1] = __expf(sc[nt][1] - mA);
            sc[nt][2] = __expf(sc[nt][2] - mB);
            sc[nt][3] = __expf(sc[nt][3] - mB);
            eA += sc[nt][0] + sc[nt][1];
            eB += sc[nt][2] + sc[nt][3];
        }
        eA += __shfl_xor_sync(0xffffffffu, eA, 1);
        eA += __shfl_xor_sync(0xffffffffu, eA, 2);
        eB += __shfl_xor_sync(0xffffffffu, eB, 1);
        eB += __shfl_xor_sync(0xffffffffu, eB, 2);
        const float invA = 1.f / eA;
        const float invB = 1.f / eB;

        uint32_t ph[13][4], pl[13][4];
#pragma unroll
        for (int kt = 0; kt < 13; kt++) {
            pack2(sc[2 * kt][0] * invA,     sc[2 * kt][1] * invA,     ph[kt][0], pl[kt][0]);
            pack2(sc[2 * kt][2] * invB,     sc[2 * kt][3] * invB,     ph[kt][1], pl[kt][1]);
            pack2(sc[2 * kt + 1][0] * invA, sc[2 * kt + 1][1] * invA, ph[kt][2], pl[kt][2]);
            pack2(sc[2 * kt + 1][2] * invB, sc[2 * kt + 1][3] * invB, ph[kt][3], pl[kt][3]);
        }

        float oc[8][4];
#pragma unroll
        for (int dt = 0; dt < 8; dt++)
#pragma unroll
            for (int e = 0; e < 4; e++) oc[dt][e] = 0.f;

#pragma unroll
        for (int dtp = 0; dtp < 4; dtp++) {
            const int vrow = dtp * 16 + (idx >> 1) * 8 + (lane & 7);
            const int vcol = (idx & 1) * 8;
#pragma unroll
            for (int kt = 0; kt < 13; kt++) {
                uint32_t vh[4], vl[4];
                ldsm_x4(vh, smem_u32(VTH + vrow * VTS + kt * 16 + vcol));
                ldsm_x4(vl, smem_u32(VTL + vrow * VTS + kt * 16 + vcol));
                mma_f16(oc[2 * dtp],     ph[kt], &vh[0]);
                mma_f16(oc[2 * dtp + 1], ph[kt], &vh[2]);
                mma_f16(oc[2 * dtp],     pl[kt], &vh[0]);
                mma_f16(oc[2 * dtp + 1], pl[kt], &vh[2]);
                mma_f16(oc[2 * dtp],     ph[kt], &vl[0]);
                mma_f16(oc[2 * dtp + 1], ph[kt], &vl[2]);
            }
        }

        float* ob = out + (size_t)b * NQ * CDIM + h * HD;
#pragma unroll
        for (int dt = 0; dt < 8; dt++) {
            const int d0 = dt * 8 + 2 * t;
            if (va) *(float2*)&ob[(size_t)qa * CDIM + d0] = make_float2(oc[dt][0], oc[dt][1]);
            if (vb) *(float2*)&ob[(size_t)qb * CDIM + d0] = make_float2(oc[dt][2], oc[dt][3]);
        }
    }
}

// ===========================================================================
extern "C" void kernel_launch(void* const* d_in, const int* in_sizes, int n_in,
                              void* d_out, int out_size)
{
    const float* x      = (const float*)d_in[0];
    const float* w_qkv  = (const float*)d_in[1];
    const float* w_proj = (const float*)d_in[2];
    const float* b_proj = (const float*)d_in[3];
    const float* rpb    = (const float*)d_in[4];
    const int*   relidx = (const int*)d_in[5];
    float* out = (float*)d_out;

    float *qkv_s, *attn_s;
    __half2 *xhi, *xlo, *whi, *wlo, *phi, *plo, *ahi, *alo;
    cudaGetSymbolAddress((void**)&qkv_s, g_qkv);
    cudaGetSymbolAddress((void**)&attn_s, g_attn);
    cudaGetSymbolAddress((void**)&xhi, g_xhi);
    cudaGetSymbolAddress((void**)&xlo, g_xlo);
    cudaGetSymbolAddress((void**)&whi, g_whi);
    cudaGetSymbolAddress((void**)&wlo, g_wlo);
    cudaGetSymbolAddress((void**)&phi, g_phi);
    cudaGetSymbolAddress((void**)&plo, g_plo);
    cudaGetSymbolAddress((void**)&ahi, g_ahi);
    cudaGetSymbolAddress((void**)&alo, g_alo);

    const int M = MTOT;   // 12608

    // 0) pre-split x, w_qkv, w_proj
    {
        int n4 = M * CDIM / 4;
        split_h<<<(n4 + 255) / 256, 256>>>((const float4*)x, xhi, xlo, n4);
        n4 = 3 * CDIM * CDIM / 4;
        split_h<<<(n4 + 255) / 256, 256>>>((const float4*)w_qkv, whi, wlo, n4);
        n4 = CDIM * CDIM / 4;
        split_h<<<(n4 + 255) / 256, 256>>>((const float4*)w_proj, phi, plo, n4);
    }

    cudaFuncSetAttribute(gemm_f16s2, cudaFuncAttributeMaxDynamicSharedMemorySize, G2SMEM);

    // 1) QKV GEMM: [M,768] x [2304,768]^T -> [M,2304]
    {
        dim3 grid((3 * CDIM) / 128, (M + 255) / 256);
        gemm_f16s2<<<grid, 256, G2SMEM>>>((const __half*)xhi, (const __half*)xlo,
                                          (const __half*)whi, (const __half*)wlo,
                                          nullptr, qkv_s, M, 3 * CDIM, CDIM);
    }

    // 2) attention (tensorized)
    {
        cudaFuncSetAttribute(attn_mma, cudaFuncAttributeMaxDynamicSharedMemorySize,
                             ATM_SMEM);
        attn_mma<<<BATCH * NH, 256, ATM_SMEM>>>(qkv_s, rpb, relidx, attn_s);
    }

    // 3) split attention output, then proj GEMM
    {
        int n4 = M * CDIM / 4;
        split_h<<<(n4 + 255) / 256, 256>>>((const float4*)attn_s, ahi, alo, n4);
        dim3 grid(CDIM / 128, (M + 255) / 256);
        gemm_f16s2<<<grid, 256, G2SMEM>>>((const __half*)ahi, (const __half*)alo,
                                          (const __half*)phi, (const __half*)plo,
                                          b_proj, out, M, CDIM, CDIM);
    }
}

// round 10
// speedup vs baseline: 1.1603x; 1.1603x over previous
#include <cuda_runtime.h>
#include <cuda_fp16.h>
#include <math_constants.h>
#include <cstdint>

// ---------------------------------------------------------------------------
// RPE_Attention: x[64,197,768] -> qkv -> per-head attention (+rel pos bias) ->
// proj.
// GEMMs: fp16 mma.sync 3-term Markidis split, 128x128 tile, 8 warps (2x4),
//        warp tile 64x32, BK=16, FOUR-stage cp.async pipeline (wait_group 2),
//        dual-tile ldsm_x4 for B.  2 CTAs/SM.
// Attention: tensorized mma.sync (R8) + direct hi/lo split output.
// ---------------------------------------------------------------------------

#define BATCH 64
#define NQ    197
#define CDIM  768
#define NH    12
#define HD    64
#define NP    196
#define MTOT  (BATCH * NQ)          // 12608

// pre-split fp16 planes
__device__ float   g_qkv[(size_t)MTOT * 3 * CDIM];
__device__ __half2 g_xhi[(size_t)MTOT * CDIM / 2];
__device__ __half2 g_xlo[(size_t)MTOT * CDIM / 2];
__device__ __half2 g_whi[(size_t)3 * CDIM * CDIM / 2];
__device__ __half2 g_wlo[(size_t)3 * CDIM * CDIM / 2];
__device__ __half2 g_phi[(size_t)CDIM * CDIM / 2];
__device__ __half2 g_plo[(size_t)CDIM * CDIM / 2];
__device__ __half2 g_ahi[(size_t)MTOT * CDIM / 2];
__device__ __half2 g_alo[(size_t)MTOT * CDIM / 2];

// ===========================================================================
// common helpers
// ===========================================================================
__device__ __forceinline__ unsigned smem_u32(const void* p) {
    return (unsigned)__cvta_generic_to_shared(p);
}
__device__ __forceinline__ void cp_async16(unsigned dst, const void* src, bool pred) {
    int sz = pred ? 16 : 0;
    asm volatile("cp.async.cg.shared.global [%0], [%1], 16, %2;\n"
                 :: "r"(dst), "l"(src), "r"(sz));
}
__device__ __forceinline__ void cp_commit() { asm volatile("cp.async.commit_group;\n"); }
__device__ __forceinline__ void cp_wait2()  { asm volatile("cp.async.wait_group 2;\n"); }

__device__ __forceinline__ void ldsm_x4(uint32_t* r, unsigned a) {
    asm volatile("ldmatrix.sync.aligned.m8n8.x4.shared.b16 {%0,%1,%2,%3}, [%4];"
                 : "=r"(r[0]), "=r"(r[1]), "=r"(r[2]), "=r"(r[3]) : "r"(a));
}
__device__ __forceinline__ void mma_f16(float* d, const uint32_t* a, const uint32_t* b) {
    asm volatile(
        "mma.sync.aligned.m16n8k16.row.col.f32.f16.f16.f32 "
        "{%0,%1,%2,%3}, {%4,%5,%6,%7}, {%8,%9}, {%0,%1,%2,%3};"
        : "+f"(d[0]), "+f"(d[1]), "+f"(d[2]), "+f"(d[3])
        : "r"(a[0]), "r"(a[1]), "r"(a[2]), "r"(a[3]), "r"(b[0]), "r"(b[1]));
}

// ===========================================================================
// split: fp32 -> (hi, lo) fp16 planes.
// ===========================================================================
__global__ void split_h(const float4* __restrict__ src, __half2* __restrict__ hi,
                        __half2* __restrict__ lo, int n4)
{
    int i = blockIdx.x * blockDim.x + threadIdx.x;
    if (i >= n4) return;
    float4 v = src[i];
    __half2 h0 = __floats2half2_rn(v.x, v.y);
    __half2 h1 = __floats2half2_rn(v.z, v.w);
    float2 f0 = __half22float2(h0);
    float2 f1 = __half22float2(h1);
    __half2 l0 = __floats2half2_rn(v.x - f0.x, v.y - f0.y);
    __half2 l1 = __floats2half2_rn(v.z - f1.x, v.w - f1.y);
    hi[2 * i]     = h0;
    hi[2 * i + 1] = h1;
    lo[2 * i]     = l0;
    lo[2 * i + 1] = l1;
}

// ===========================================================================
// fp16-split GEMM (NT), v3: BM=BN=128, BK=16, 256 thr = 8 warps (2x4),
// warp tile 64x32.  4-stage cp.async pipeline, dual-tile ldsm_x4 for B.
// Stage layout (halfs, stride 24): Ahi[128x24] Alo Bhi[128x24] Blo
// ===========================================================================
#define S24     24
#define PL3     (128 * S24)            // 3072 halfs per plane
#define STG_H   (4 * PL3)              // 12288 halfs per stage
#define STG_B   (STG_H * 2)            // 24576 bytes
#define G3SMEM  (4 * STG_B)            // 98304 bytes

__global__ __launch_bounds__(256, 2) void gemm_f16s3(
    const __half* __restrict__ Ahi, const __half* __restrict__ Alo,
    const __half* __restrict__ Bhi, const __half* __restrict__ Blo,
    const float* __restrict__ bias, float* __restrict__ C,
    int M, int N, int K)
{
    extern __shared__ __half smg[];

    const int tid  = threadIdx.x;
    const int lane = tid & 31;
    const int wid  = tid >> 5;
    const int wm   = wid & 1;          // 64-row band
    const int wn   = wid >> 1;         // 32-col band (0..3)
    const int bm   = blockIdx.y * 128;
    const int bn   = blockIdx.x * 128;
    const unsigned sbase = smem_u32(smg);

    // loader: thread -> one row-half (16B) per plane
    const int lrow = tid >> 1;
    const int lh   = tid & 1;
    const bool aok = (bm + lrow) < M;
    const __half* gAh = Ahi + (size_t)(aok ? bm + lrow : 0) * K + lh * 8;
    const __half* gAl = Alo + (size_t)(aok ? bm + lrow : 0) * K + lh * 8;
    const __half* gBh = Bhi + (size_t)(bn + lrow) * K + lh * 8;
    const __half* gBl = Blo + (size_t)(bn + lrow) * K + lh * 8;
    const unsigned sA = sbase + (unsigned)(lrow * S24 + lh * 8) * 2u;
    const unsigned sB = sA + (unsigned)(2 * PL3) * 2u;

    const int nIter = K / 16;          // 48

    auto load_stage = [&](int it3) {
        const unsigned off = (unsigned)(it3 & 3) * STG_B;
        const int k0 = it3 * 16;
        cp_async16(sA + off,           gAh + k0, aok);
        cp_async16(sA + off + PL3 * 2, gAl + k0, aok);
        cp_async16(sB + off,           gBh + k0, true);
        cp_async16(sB + off + PL3 * 2, gBl + k0, true);
    };

    float acc[4][4][4];
#pragma unroll
    for (int i = 0; i < 4; i++)
#pragma unroll
        for (int j = 0; j < 4; j++)
#pragma unroll
            for (int r = 0; r < 4; r++) acc[i][j][r] = 0.f;

    // prologue: stages 0,1,2 in flight
    load_stage(0); cp_commit();
    load_stage(1); cp_commit();
    load_stage(2); cp_commit();

    // fragment addresses
    const int arow = wm * 64 + (lane & 15);
    const int acol = (lane >> 4) * 8;
    const int q    = lane >> 3;                         // ldsm_x4 group
    const int brow = wn * 32 + (q >> 1) * 8 + (lane & 7);
    const int bcol = (q & 1) * 8;

    for (int it = 0; it < nIter; it++) {
        cp_wait2();            // stage `it` resident (pending <= {it+1, it+2})
        __syncthreads();       // visible to all; all done with stage it-1

        if (it + 3 < nIter) load_stage(it + 3);
        cp_commit();           // unconditional: keep group count stable

        const __half* st  = smg + (it & 3) * STG_H;
        const __half* sa0 = st;
        const __half* sa1 = st + PL3;
        const __half* sb0 = st + 2 * PL3;
        const __half* sb1 = st + 3 * PL3;

        // B fragments: 2 pairs x 2 planes (each x4 covers 2 n-tiles)
        uint32_t bh[2][4], bl[2][4];
#pragma unroll
        for (int p = 0; p < 2; p++) {
            ldsm_x4(bh[p], smem_u32(sb0 + (brow + p * 16) * S24 + bcol));
            ldsm_x4(bl[p], smem_u32(sb1 + (brow + p * 16) * S24 + bcol));
        }
#pragma unroll
        for (int mt = 0; mt < 4; mt++) {
            uint32_t ah[4], al[4];
            ldsm_x4(ah, smem_u32(sa0 + (arow + mt * 16) * S24 + acol));
            ldsm_x4(al, smem_u32(sa1 + (arow + mt * 16) * S24 + acol));
#pragma unroll
            for (int nt = 0; nt < 4; nt++)
                mma_f16(acc[mt][nt], ah, &bh[nt >> 1][(nt & 1) * 2]);
#pragma unroll
            for (int nt = 0; nt < 4; nt++)
                mma_f16(acc[mt][nt], al, &bh[nt >> 1][(nt & 1) * 2]);
#pragma unroll
            for (int nt = 0; nt < 4; nt++)
                mma_f16(acc[mt][nt], ah, &bl[nt >> 1][(nt & 1) * 2]);
        }
    }

    // epilogue
    const int g = lane >> 2;
    const int t = lane & 3;
#pragma unroll
    for (int mt = 0; mt < 4; mt++) {
        const int r0 = bm + wm * 64 + mt * 16 + g;
#pragma unroll
        for (int nt = 0; nt < 4; nt++) {
            const int col = bn + wn * 32 + nt * 8 + 2 * t;
            const float bv0 = bias ? bias[col]     : 0.f;
            const float bv1 = bias ? bias[col + 1] : 0.f;
            if (r0 < M) {
                float2 v = make_float2(acc[mt][nt][0] + bv0, acc[mt][nt][1] + bv1);
                *(float2*)&C[(size_t)r0 * N + col] = v;
            }
            if (r0 + 8 < M) {
                float2 v = make_float2(acc[mt][nt][2] + bv0, acc[mt][nt][3] + bv1);
                *(float2*)&C[(size_t)(r0 + 8) * N + col] = v;
            }
        }
    }
}

// ===========================================================================
// Tensorized attention (R8) + direct hi/lo split output.
// ===========================================================================
#define NPAD   208
#define QKS    72
#define VTS    232
#define QH_OFF 0
#define QL_OFF (NPAD * QKS)
#define KH_OFF (2 * NPAD * QKS)
#define KL_OFF (3 * NPAD * QKS)
#define VTH_OFF (4 * NPAD * QKS)
#define VTL_OFF (VTH_OFF + HD * VTS)
#define ATM_HALFS (VTL_OFF + HD * VTS)
#define ATM_SMEM  (ATM_HALFS * 2 + 736 * 4)

__device__ __forceinline__ void pack2(float x, float y, uint32_t& hi, uint32_t& lo) {
    __half2 h = __floats2half2_rn(x, y);
    float2 f = __half22float2(h);
    __half2 l = __floats2half2_rn(x - f.x, y - f.y);
    hi = *reinterpret_cast<uint32_t*>(&h);
    lo = *reinterpret_cast<uint32_t*>(&l);
}

__global__ __launch_bounds__(256, 1) void attn_mma(
    const float* __restrict__ qkv, const float* __restrict__ rpb_table,
    const int* __restrict__ rel_idx,
    uint32_t* __restrict__ ohi, uint32_t* __restrict__ olo)
{
    extern __shared__ __align__(16) __half sma[];
    __half* QH  = sma + QH_OFF;
    __half* QL  = sma + QL_OFF;
    __half* KH  = sma + KH_OFF;
    __half* KL  = sma + KL_OFF;
    __half* VTH = sma + VTH_OFF;
    __half* VTL = sma + VTL_OFF;
    float*  bias_s = (float*)(sma + ATM_HALFS);

    const int tid  = threadIdx.x;
    const int lane = tid & 31;
    const int wid  = tid >> 5;
    const int b = blockIdx.x / NH;
    const int h = blockIdx.x % NH;

    const float* base0 = qkv + (size_t)b * NQ * (3 * CDIM) + h * HD;
    for (int i = tid; i < NPAD * HD; i += 256) {
        const int n = i >> 6, d = i & 63;
        float qv = 0.f, kv = 0.f, vv = 0.f;
        if (n < NQ) {
            const float* p = base0 + (size_t)n * (3 * CDIM) + d;
            qv = p[0] * 0.125f;
            kv = p[CDIM];
            vv = p[2 * CDIM];
        }
        __half qh_ = __float2half_rn(qv);
        QH[n * QKS + d] = qh_;
        QL[n * QKS + d] = __float2half_rn(qv - __half2float(qh_));
        __half kh_ = __float2half_rn(kv);
        KH[n * QKS + d] = kh_;
        KL[n * QKS + d] = __float2half_rn(kv - __half2float(kh_));
        __half vh_ = __float2half_rn(vv);
        VTH[d * VTS + n] = vh_;
        VTL[d * VTS + n] = __float2half_rn(vv - __half2float(vh_));
    }
    for (int i = tid; i < 729; i += 256) bias_s[i] = rpb_table[i * NH + h];
    __syncthreads();

    const int g = lane >> 2;
    const int t = lane & 3;
    const int idx = lane >> 3;

    for (int mt = wid; mt < 13; mt += 8) {
        const int q0 = mt * 16;

        uint32_t qfh[4][4], qfl[4][4];
        {
            const int row = q0 + (lane & 15);
            const int col = (lane >> 4) * 8;
#pragma unroll
            for (int kt = 0; kt < 4; kt++) {
                ldsm_x4(qfh[kt], smem_u32(QH + row * QKS + kt * 16 + col));
                ldsm_x4(qfl[kt], smem_u32(QL + row * QKS + kt * 16 + col));
            }
        }

        float sc[26][4];
#pragma unroll
        for (int nt = 0; nt < 26; nt++)
#pragma unroll
            for (int e = 0; e < 4; e++) sc[nt][e] = 0.f;

#pragma unroll
        for (int ntp = 0; ntp < 13; ntp++) {
            const int row = ntp * 16 + (idx >> 1) * 8 + (lane & 7);
            const int col = (idx & 1) * 8;
            uint32_t kf[4][4], lf[4][4];
#pragma unroll
            for (int kt = 0; kt < 4; kt++) {
                ldsm_x4(kf[kt], smem_u32(KH + row * QKS + kt * 16 + col));
                ldsm_x4(lf[kt], smem_u32(KL + row * QKS + kt * 16 + col));
            }
#pragma unroll
            for (int kt = 0; kt < 4; kt++) {
                mma_f16(sc[2 * ntp],     qfh[kt], &kf[kt][0]);
                mma_f16(sc[2 * ntp + 1], qfh[kt], &kf[kt][2]);
                mma_f16(sc[2 * ntp],     qfl[kt], &kf[kt][0]);
                mma_f16(sc[2 * ntp + 1], qfl[kt], &kf[kt][2]);
                mma_f16(sc[2 * ntp],     qfh[kt], &lf[kt][0]);
                mma_f16(sc[2 * ntp + 1], qfh[kt], &lf[kt][2]);
            }
        }

        const int qa = q0 + g;
        const int qb = q0 + g + 8;
        const bool va = qa < NQ;
        const bool vb = qb < NQ;
#pragma unroll
        for (int nt = 0; nt < 26; nt++) {
            const int j0 = nt * 8 + 2 * t;
            const int j1 = j0 + 1;
            {
                float s = sc[nt][0];
                if (!va) s = 0.f;
                else if (j0 >= NQ) s = -CUDART_INF_F;
                else if (qa > 0 && j0 > 0)
                    s += bias_s[__ldg(rel_idx + (qa - 1) * NP + (j0 - 1))];
                sc[nt][0] = s;
            }
            {
                float s = sc[nt][1];
                if (!va) s = 0.f;
                else if (j1 >= NQ) s = -CUDART_INF_F;
                else if (qa > 0)
                    s += bias_s[__ldg(rel_idx + (qa - 1) * NP + (j1 - 1))];
                sc[nt][1] = s;
            }
            {
                float s = sc[nt][2];
                if (!vb) s = 0.f;
                else if (j0 >= NQ) s = -CUDART_INF_F;
                else if (qb > 0 && j0 > 0)
                    s += bias_s[__ldg(rel_idx + (qb - 1) * NP + (j0 - 1))];
                sc[nt][2] = s;
            }
            {
                float s = sc[nt][3];
                if (!vb) s = 0.f;
                else if (j1 >= NQ) s = -CUDART_INF_F;
                else if (qb > 0)
                    s += bias_s[__ldg(rel_idx + (qb - 1) * NP + (j1 - 1))];
                sc[nt][3] = s;
            }
        }

        float mA = -CUDART_INF_F, mB = -CUDART_INF_F;
#pragma unroll
        for (int nt = 0; nt < 26; nt++) {
            mA = fmaxf(mA, fmaxf(sc[nt][0], sc[nt][1]));
            mB = fmaxf(mB, fmaxf(sc[nt][2], sc[nt][3]));
        }
        mA = fmaxf(mA, __shfl_xor_sync(0xffffffffu, mA, 1));
        mA = fmaxf(mA, __shfl_xor_sync(0xffffffffu, mA, 2));
        mB = fmaxf(mB, __shfl_xor_sync(0xffffffffu, mB, 1));
        mB = fmaxf(mB, __shfl_xor_sync(0xffffffffu, mB, 2));

        float eA = 0.f, eB = 0.f;
#pragma unroll
        for (int nt = 0; nt < 26; nt++) {
            sc[nt][0] = __expf(sc[nt][0] - mA);
            sc[nt][1] = __expf(sc[nt][1] - mA);
            sc[nt][2] = __expf(sc[nt][2] - mB);
            sc[nt][3] = __expf(sc[nt][3] - mB);
            eA += sc[nt][0] + sc[nt][1];
            eB += sc[nt][2] + sc[nt][3];
        }
        eA += __shfl_xor_sync(0xffffffffu, eA, 1);
        eA += __shfl_xor_sync(0xffffffffu, eA, 2);
        eB += __shfl_xor_sync(0xffffffffu, eB, 1);
        eB += __shfl_xor_sync(0xffffffffu, eB, 2);
        const float invA = 1.f / eA;
        const float invB = 1.f / eB;

        uint32_t ph[13][4], pl[13][4];
#pragma unroll
        for (int kt = 0; kt < 13; kt++) {
            pack2(sc[2 * kt][0] * invA,     sc[2 * kt][1] * invA,     ph[kt][0], pl[kt][0]);
            pack2(sc[2 * kt][2] * invB,     sc[2 * kt][3] * invB,     ph[kt][1], pl[kt][1]);
            pack2(sc[2 * kt + 1][0] * invA, sc[2 * kt + 1][1] * invA, ph[kt][2], pl[kt][2]);
            pack2(sc[2 * kt + 1][2] * invB, sc[2 * kt + 1][3] * invB, ph[kt][3], pl[kt][3]);
        }

        float oc[8][4];
#pragma unroll
        for (int dt = 0; dt < 8; dt++)
#pragma unroll
            for (int e = 0; e < 4; e++) oc[dt][e] = 0.f;

#pragma unroll
        for (int dtp = 0; dtp < 4; dtp++) {
            const int vrow = dtp * 16 + (idx >> 1) * 8 + (lane & 7);
            const int vcol = (idx & 1) * 8;
#pragma unroll
            for (int kt = 0; kt < 13; kt++) {
                uint32_t vh[4], vl[4];
                ldsm_x4(vh, smem_u32(VTH + vrow * VTS + kt * 16 + vcol));
                ldsm_x4(vl, smem_u32(VTL + vrow * VTS + kt * 16 + vcol));
                mma_f16(oc[2 * dtp],     ph[kt], &vh[0]);
                mma_f16(oc[2 * dtp + 1], ph[kt], &vh[2]);
                mma_f16(oc[2 * dtp],     pl[kt], &vh[0]);
                mma_f16(oc[2 * dtp + 1], pl[kt], &vh[2]);
                mma_f16(oc[2 * dtp],     ph[kt], &vl[0]);
                mma_f16(oc[2 * dtp + 1], ph[kt], &vl[2]);
            }
        }

        // store: split into hi/lo fp16 planes directly (proj GEMM A operand)
#pragma unroll
        for (int dt = 0; dt < 8; dt++) {
            const int d0 = dt * 8 + 2 * t;
            if (va) {
                uint32_t hb, lb;
                pack2(oc[dt][0], oc[dt][1], hb, lb);
                const size_t ei = (((size_t)b * NQ + qa) * CDIM + h * HD + d0) >> 1;
                ohi[ei] = hb; olo[ei] = lb;
            }
            if (vb) {
                uint32_t hb, lb;
                pack2(oc[dt][2], oc[dt][3], hb, lb);
                const size_t ei = (((size_t)b * NQ + qb) * CDIM + h * HD + d0) >> 1;
                ohi[ei] = hb; olo[ei] = lb;
            }
        }
    }
}

// ===========================================================================
extern "C" void kernel_launch(void* const* d_in, const int* in_sizes, int n_in,
                              void* d_out, int out_size)
{
    const float* x      = (const float*)d_in[0];
    const float* w_qkv  = (const float*)d_in[1];
    const float* w_proj = (const float*)d_in[2];
    const float* b_proj = (const float*)d_in[3];
    const float* rpb    = (const float*)d_in[4];
    const int*   relidx = (const int*)d_in[5];
    float* out = (float*)d_out;

    float* qkv_s;
    __half2 *xhi, *xlo, *whi, *wlo, *phi, *plo, *ahi, *alo;
    cudaGetSymbolAddress((void**)&qkv_s, g_qkv);
    cudaGetSymbolAddress((void**)&xhi, g_xhi);
    cudaGetSymbolAddress((void**)&xlo, g_xlo);
    cudaGetSymbolAddress((void**)&whi, g_whi);
    cudaGetSymbolAddress((void**)&wlo, g_wlo);
    cudaGetSymbolAddress((void**)&phi, g_phi);
    cudaGetSymbolAddress((void**)&plo, g_plo);
    cudaGetSymbolAddress((void**)&ahi, g_ahi);
    cudaGetSymbolAddress((void**)&alo, g_alo);

    const int M = MTOT;   // 12608

    // 0) pre-split x, w_qkv, w_proj
    {
        int n4 = M * CDIM / 4;
        split_h<<<(n4 + 255) / 256, 256>>>((const float4*)x, xhi, xlo, n4);
        n4 = 3 * CDIM * CDIM / 4;
        split_h<<<(n4 + 255) / 256, 256>>>((const float4*)w_qkv, whi, wlo, n4);
        n4 = CDIM * CDIM / 4;
        split_h<<<(n4 + 255) / 256, 256>>>((const float4*)w_proj, phi, plo, n4);
    }

    cudaFuncSetAttribute(gemm_f16s3, cudaFuncAttributeMaxDynamicSharedMemorySize, G3SMEM);

    // 1) QKV GEMM: [M,768] x [2304,768]^T -> [M,2304]
    {
        dim3 grid((3 * CDIM) / 128, (M + 127) / 128);
        gemm_f16s3<<<grid, 256, G3SMEM>>>((const __half*)xhi, (const __half*)xlo,
                                          (const __half*)whi, (const __half*)wlo,
                                          nullptr, qkv_s, M, 3 * CDIM, CDIM);
    }

    // 2) attention (tensorized; emits split hi/lo planes directly)
    {
        cudaFuncSetAttribute(attn_mma, cudaFuncAttributeMaxDynamicSharedMemorySize,
                             ATM_SMEM);
        attn_mma<<<BATCH * NH, 256, ATM_SMEM>>>(qkv_s, rpb, relidx,
                                                (uint32_t*)ahi, (uint32_t*)alo);
    }

    // 3) proj GEMM: [M,768] x [768,768]^T + bias -> out
    {
        dim3 grid(CDIM / 128, (M + 127) / 128);
        gemm_f16s3<<<grid, 256, G3SMEM>>>((const __half*)ahi, (const __half*)alo,
                                          (const __half*)phi, (const __half*)plo,
                                          b_proj, out, M, CDIM, CDIM);
    }
}